// round 11
// baseline (speedup 1.0000x reference)
#include <cuda_runtime.h>
#include <cuda_bf16.h>
#include <cuda_fp16.h>
#include <math.h>
#include <stdint.h>

#define TFULL 2048
#define DM    1024

// Scratch (static device globals — no allocation allowed)
__device__ __half g_x16[2 * TFULL * DM];       // x fp16
__device__ __half g_wc16[1536 * 1024];         // concat WQ|WK|WV fp16
__device__ __half g_wo16[1024 * 1024];         // WO fp16
__device__ __half g_att16[2 * TFULL * DM];     // attn out fp16
__device__ __half g_q16[2 * 16 * TFULL * 64];  // [b][h][t][64]
__device__ __half g_k16[2 * 4 * TFULL * 64];   // [b][g][t][64]
__device__ __half g_v16t[2 * 4 * 64 * TFULL];  // [b][g][dim][t]

// ===========================================================================
// Helpers
// ===========================================================================
__device__ __forceinline__ uint32_t smem_u32(const void* p) {
    uint32_t a;
    asm("{ .reg .u64 t; cvta.to.shared.u64 t, %1; cvt.u32.u64 %0, t; }"
        : "=r"(a) : "l"(p));
    return a;
}
__device__ __forceinline__ void ldsm_x4(uint32_t& r0, uint32_t& r1, uint32_t& r2,
                                        uint32_t& r3, uint32_t addr) {
    asm volatile("ldmatrix.sync.aligned.m8n8.x4.shared.b16 {%0,%1,%2,%3}, [%4];"
                 : "=r"(r0), "=r"(r1), "=r"(r2), "=r"(r3) : "r"(addr));
}
__device__ __forceinline__ void mma_f16(float* c, const uint32_t* a, const uint32_t* b) {
    asm volatile(
        "mma.sync.aligned.m16n8k16.row.col.f32.f16.f16.f32 "
        "{%0,%1,%2,%3}, {%4,%5,%6,%7}, {%8,%9}, {%0,%1,%2,%3};"
        : "+f"(c[0]), "+f"(c[1]), "+f"(c[2]), "+f"(c[3])
        : "r"(a[0]), "r"(a[1]), "r"(a[2]), "r"(a[3]), "r"(b[0]), "r"(b[1]));
}
__device__ __forceinline__ uint32_t pack_f16(float a, float b) {
    uint32_t r;
    asm("cvt.rn.f16x2.f32 %0, %1, %2;" : "=r"(r) : "f"(b), "f"(a));
    return r;
}
__device__ __forceinline__ void cp16(uint32_t dst, const void* src) {
    asm volatile("cp.async.cg.shared.global [%0], [%1], 16;"
                 :: "r"(dst), "l"(src) : "memory");
}
#define CP_COMMIT() asm volatile("cp.async.commit_group;" ::: "memory")
#define CP_WAIT(n)  asm volatile("cp.async.wait_group %0;" :: "n"(n) : "memory")
#define SW128(off) ((off) ^ (((off) >> 3) & 0x70))

#define QSCALE 0.18033688011112043f   // log2(e) / 8
#define ROPE_C (-0.28782313662425572f) // -ln(10000)/32

// ===========================================================================
// Fused convert: all fp32 sources -> fp16 in ONE launch.
// ===========================================================================
__global__ void convert_all(const float4* __restrict__ x, const float4* __restrict__ wq,
                            const float4* __restrict__ wk, const float4* __restrict__ wv,
                            const float4* __restrict__ wo,
                            __half* __restrict__ x16, __half* __restrict__ wc16,
                            __half* __restrict__ wo16) {
    const int i = blockIdx.x * 256 + threadIdx.x;
    const float4* src;
    __half* dst;
    size_t off;
    if (i < 1048576)      { src = x + i;               dst = x16;  off = (size_t)i * 4; }
    else if (i < 1310720) { const int j = i - 1048576; src = wq + j; dst = wc16; off = (size_t)j * 4; }
    else if (i < 1376256) { const int j = i - 1310720; src = wk + j; dst = wc16; off = 1048576 + (size_t)j * 4; }
    else if (i < 1441792) { const int j = i - 1376256; src = wv + j; dst = wc16; off = 1310720 + (size_t)j * 4; }
    else                  { const int j = i - 1441792; src = wo + j; dst = wo16; off = (size_t)j * 4; }
    const float4 v = *src;
    *(uint2*)(dst + off) = make_uint2(pack_f16(v.x, v.y), pack_f16(v.z, v.w));
}

// ===========================================================================
// GEMM mainloop shared macro body (fp16, CTA 128x128, K-chunk 64, 3-stage)
// ===========================================================================
#define GK 1024
#define SM_STAGE 32768
#define SM_GEMM (3 * SM_STAGE)

#define GEMM_MAINLOOP(A, B)                                                    \
    const uint32_t smb = smem_u32(sm);                                         \
    const int tid = threadIdx.x;                                               \
    const int lid = tid & 31;                                                  \
    const int wid = tid >> 5;                                                  \
    const int wm = wid & 3;                                                    \
    const int wn = wid >> 2;                                                   \
    const int m0 = blockIdx.y * 128;                                           \
    const int n0 = blockIdx.x * 128;                                           \
    float acc[2][8][4];                                                        \
    _Pragma("unroll")                                                          \
    for (int s = 0; s < 2; s++)                                                \
        _Pragma("unroll")                                                      \
        for (int j = 0; j < 8; j++)                                            \
            _Pragma("unroll")                                                  \
            for (int q = 0; q < 4; q++) acc[s][j][q] = 0.f;                    \
    ISSUE(0, 0);                                                               \
    ISSUE(1, 1);                                                               \
    int stage = 0;                                                             \
    for (int c = 0; c < 16; c++) {                                             \
        if (c == 15) { CP_WAIT(0); } else { CP_WAIT(1); }                      \
        __syncthreads();                                                       \
        if (c + 2 < 16) {                                                      \
            const int ns = (stage + 2 >= 3) ? stage - 1 : stage + 2;           \
            ISSUE(c + 2, ns);                                                  \
        }                                                                      \
        const uint32_t abase = smb + stage * SM_STAGE;                         \
        const uint32_t bbase = abase + 16384;                                  \
        _Pragma("unroll")                                                      \
        for (int kk = 0; kk < 4; kk++) {                                       \
            uint32_t ah[2][4];                                                 \
            _Pragma("unroll")                                                  \
            for (int sub = 0; sub < 2; sub++) {                                \
                const uint32_t row = (uint32_t)(wm * 32 + sub * 16 + (lid & 15)); \
                const uint32_t col2 = (uint32_t)((kk * 16 + ((lid >> 4) << 3)) * 2); \
                ldsm_x4(ah[sub][0], ah[sub][1], ah[sub][2], ah[sub][3],        \
                        abase + SW128(row * 128 + col2));                      \
            }                                                                  \
            _Pragma("unroll")                                                  \
            for (int nt = 0; nt < 4; nt++) {                                   \
                const uint32_t rown =                                          \
                    (uint32_t)(wn * 64 + nt * 16 + (lid & 7) + ((lid & 16) ? 8 : 0)); \
                const uint32_t colb = (uint32_t)((kk * 16 + ((lid & 8) ? 8 : 0)) * 2); \
                uint32_t b[4];                                                 \
                ldsm_x4(b[0], b[1], b[2], b[3], bbase + SW128(rown * 128 + colb)); \
                _Pragma("unroll")                                              \
                for (int sub = 0; sub < 2; sub++) {                            \
                    mma_f16(acc[sub][2 * nt],     ah[sub], b);                 \
                    mma_f16(acc[sub][2 * nt + 1], ah[sub], b + 2);             \
                }                                                              \
            }                                                                  \
        }                                                                      \
        stage = (stage + 1 == 3) ? 0 : stage + 1;                              \
    }

#define ISSUE(c, stage)                                                        \
    {                                                                          \
        const int kc = (c) * 64;                                               \
        const uint32_t sbase = smb + (stage) * SM_STAGE;                       \
        _Pragma("unroll")                                                      \
        for (int u = 0; u < 4; u++) {                                          \
            const int idx = tid + 256 * u;                                     \
            const int row = idx >> 3, c8 = idx & 7;                            \
            const uint32_t doff = SW128((uint32_t)(row * 128 + c8 * 16));      \
            cp16(sbase + doff, A + (size_t)(m0 + row) * GK + kc + c8 * 8);     \
            cp16(sbase + 16384 + doff,                                         \
                 B + (size_t)(n0 + row) * GK + kc + c8 * 8);                   \
        }                                                                      \
        CP_COMMIT();                                                           \
    }

// ===========================================================================
// QKV GEMM with fused RoPE + fp16 emit. No fp32 C output at all.
// Column ranges: [0,1024) Q -> rope+scale, [1024,1280) K -> rope,
// [1280,1536) V -> transposed store. Boundaries are CTA-tile aligned.
// ===========================================================================
__global__ __launch_bounds__(256, 2)
void gemm_qkv(const __half* __restrict__ A, const __half* __restrict__ B,
              const int* __restrict__ tpos,
              __half* __restrict__ Q16, __half* __restrict__ K16,
              __half* __restrict__ V16t) {
    extern __shared__ char sm[];
    GEMM_MAINLOOP(A, B)

    // ---- fused RoPE epilogue ----
    const int tr = lid >> 2;
    const int tc = (lid & 3) * 2;
#pragma unroll
    for (int sub = 0; sub < 2; sub++) {
#pragma unroll
        for (int half = 0; half < 2; half++) {
            const int m = m0 + wm * 32 + sub * 16 + tr + half * 8;
            const int bb = m >> 11;
            const int t = m & (TFULL - 1);
            const float pos = (float)tpos[t];
#pragma unroll
            for (int j = 0; j < 8; j++) {
                const int n = n0 + wn * 64 + j * 8 + tc;
                const float v0 = acc[sub][j][2 * half];
                const float v1 = acc[sub][j][2 * half + 1];
                if (n < 1280) {
                    const int pp = (n & 63) >> 1;
                    const float ang = pos * __expf(ROPE_C * (float)pp);
                    float s, c;
                    sincosf(ang, &s, &c);
                    const float r1 = v0 * c - v1 * s;
                    const float r2 = v0 * s + v1 * c;
                    if (n < 1024) {
                        const int head = n >> 6;
                        *(uint32_t*)(Q16 +
                            ((size_t)((bb * 16 + head) * TFULL + t)) * 64 + (n & 63)) =
                            pack_f16(r1 * QSCALE, r2 * QSCALE);
                    } else {
                        const int g = (n - 1024) >> 6;
                        *(uint32_t*)(K16 +
                            ((size_t)((bb * 4 + g) * TFULL + t)) * 64 + (n & 63)) =
                            pack_f16(r1, r2);
                    }
                } else {
                    const int np = n - 1280;
                    const int g = np >> 6, d = np & 63;
                    V16t[((size_t)((bb * 4 + g) * 64 + d)) * TFULL + t] = __float2half(v0);
                    V16t[((size_t)((bb * 4 + g) * 64 + d + 1)) * TFULL + t] = __float2half(v1);
                }
            }
        }
    }
}

// ===========================================================================
// Plain fp16 GEMM -> fp32 C (for output projection)
// ===========================================================================
__global__ __launch_bounds__(256, 2)
void gemm_f16(const __half* __restrict__ A, const __half* __restrict__ B,
              float* __restrict__ C, int ldc) {
    extern __shared__ char sm[];
    GEMM_MAINLOOP(A, B)

    const int tr = lid >> 2;
    const int tc = (lid & 3) * 2;
#pragma unroll
    for (int sub = 0; sub < 2; sub++) {
        const int m = m0 + wm * 32 + sub * 16 + tr;
#pragma unroll
        for (int j = 0; j < 8; j++) {
            const int n = n0 + wn * 64 + j * 8 + tc;
            *(float2*)(C + (size_t)m * ldc + n) =
                make_float2(acc[sub][j][0], acc[sub][j][1]);
            *(float2*)(C + (size_t)(m + 8) * ldc + n) =
                make_float2(acc[sub][j][2], acc[sub][j][3]);
        }
    }
}
#undef ISSUE

// ===========================================================================
// fp16 mma flash attention, cp.async double-buffered K/V -> fp16 output
// ===========================================================================
__global__ __launch_bounds__(128)
void attn_mma(const __half* __restrict__ Q16, const __half* __restrict__ K16,
              const __half* __restrict__ V16t, __half* __restrict__ O16) {
    __shared__ __align__(1024) char smQ[8192];
    __shared__ __align__(1024) char smK[2][8192];
    __shared__ __align__(1024) char smV[2][8192];
    const int tid = threadIdx.x, lid = tid & 31, w = tid >> 5;
    const int i0 = blockIdx.x * 64;
    const int h = blockIdx.y, bb = blockIdx.z, g = h >> 2;

    const uint32_t smbQ = smem_u32(smQ);
    const uint32_t smbK = smem_u32(smK);
    const uint32_t smbV = smem_u32(smV);
    const __half* kgb = K16 + ((size_t)((bb * 4 + g) * TFULL)) * 64;
    const __half* vgb = V16t + ((size_t)((bb * 4 + g) * 64)) * TFULL;
    const int j0 = (i0 - 512 > 0) ? (i0 - 512) : 0;
    const int nchunks = (i0 - j0) / 64 + 1;

#define ISSUE_KV(jc, buf)                                                      \
    {                                                                          \
        _Pragma("unroll")                                                      \
        for (int u = 0; u < 4; u++) {                                          \
            const int idx = tid + 128 * u;                                     \
            const int r = idx >> 3, cc = idx & 7;                              \
            const uint32_t d = (uint32_t)(buf) * 8192 +                        \
                               SW128((uint32_t)(r * 128 + cc * 16));           \
            cp16(smbK + d, kgb + (size_t)((jc) + r) * 64 + cc * 8);            \
            cp16(smbV + d, vgb + (size_t)r * TFULL + (jc) + cc * 8);           \
        }                                                                      \
        CP_COMMIT();                                                           \
    }

    ISSUE_KV(j0, 0);
    const __half* qg = Q16 + ((size_t)((bb * 16 + h) * TFULL + i0)) * 64;
#pragma unroll
    for (int u = 0; u < 4; u++) {
        const int idx = tid + 128 * u;
        const int r = idx >> 3, c = idx & 7;
        *(uint4*)(smQ + SW128((uint32_t)(r * 128 + c * 16))) =
            *(const uint4*)(qg + (size_t)r * 64 + c * 8);
    }
    __syncthreads();

    uint32_t qa[4][4];
#pragma unroll
    for (int ks = 0; ks < 4; ks++) {
        const uint32_t off =
            (uint32_t)((w * 16 + (lid & 15)) * 128 + (ks * 16 + ((lid >> 4) << 3)) * 2);
        ldsm_x4(qa[ks][0], qa[ks][1], qa[ks][2], qa[ks][3], smbQ + SW128(off));
    }

    float oacc[8][4];
#pragma unroll
    for (int j = 0; j < 8; j++)
#pragma unroll
        for (int q = 0; q < 4; q++) oacc[j][q] = 0.f;
    float m0 = -1e30f, m1 = -1e30f, l0 = 0.f, l1 = 0.f;

    for (int ci = 0; ci < nchunks; ci++) {
        const int jc = j0 + ci * 64;
        const int buf = ci & 1;
        if (ci + 1 < nchunks) {
            ISSUE_KV(jc + 64, buf ^ 1);
            CP_WAIT(1);
        } else {
            CP_WAIT(0);
        }
        __syncthreads();

        const uint32_t kb_base = smbK + buf * 8192;
        const uint32_t vb_base = smbV + buf * 8192;

        float sacc[8][4];
#pragma unroll
        for (int j = 0; j < 8; j++)
#pragma unroll
            for (int q = 0; q < 4; q++) sacc[j][q] = 0.f;
#pragma unroll
        for (int ks = 0; ks < 4; ks++) {
            uint32_t kb[8][2];
#pragma unroll
            for (int nt = 0; nt < 4; nt++) {
                const uint32_t off =
                    (uint32_t)((nt * 16 + (lid & 7) + ((lid & 16) ? 8 : 0)) * 128 +
                               (ks * 16 + ((lid & 8) ? 8 : 0)) * 2);
                uint32_t r0, r1, r2, r3;
                ldsm_x4(r0, r1, r2, r3, kb_base + SW128(off));
                kb[nt * 2][0] = r0; kb[nt * 2][1] = r1;
                kb[nt * 2 + 1][0] = r2; kb[nt * 2 + 1][1] = r3;
            }
#pragma unroll
            for (int j = 0; j < 8; j++) mma_f16(sacc[j], qa[ks], kb[j]);
        }

        if (jc == i0 || i0 - jc == 512) {
            const int r0 = i0 + w * 16 + (lid >> 2), r1 = r0 + 8;
#pragma unroll
            for (int j = 0; j < 8; j++) {
                const int c0 = jc + j * 8 + 2 * (lid & 3);
                if (c0 > r0 || r0 - c0 > 512)         sacc[j][0] = -1e30f;
                if (c0 + 1 > r0 || r0 - c0 - 1 > 512) sacc[j][1] = -1e30f;
                if (c0 > r1 || r1 - c0 > 512)         sacc[j][2] = -1e30f;
                if (c0 + 1 > r1 || r1 - c0 - 1 > 512) sacc[j][3] = -1e30f;
            }
        }

        float mx0 = -1e30f, mx1 = -1e30f;
#pragma unroll
        for (int j = 0; j < 8; j++) {
            mx0 = fmaxf(mx0, fmaxf(sacc[j][0], sacc[j][1]));
            mx1 = fmaxf(mx1, fmaxf(sacc[j][2], sacc[j][3]));
        }
        mx0 = fmaxf(mx0, __shfl_xor_sync(0xffffffff, mx0, 1));
        mx0 = fmaxf(mx0, __shfl_xor_sync(0xffffffff, mx0, 2));
        mx1 = fmaxf(mx1, __shfl_xor_sync(0xffffffff, mx1, 1));
        mx1 = fmaxf(mx1, __shfl_xor_sync(0xffffffff, mx1, 2));
        const float mn0 = fmaxf(m0, mx0), mn1 = fmaxf(m1, mx1);
        const float corr0 = exp2f(m0 - mn0), corr1 = exp2f(m1 - mn1);
        float sum0 = 0.f, sum1 = 0.f;
#pragma unroll
        for (int j = 0; j < 8; j++) {
            sacc[j][0] = exp2f(sacc[j][0] - mn0);
            sacc[j][1] = exp2f(sacc[j][1] - mn0);
            sacc[j][2] = exp2f(sacc[j][2] - mn1);
            sacc[j][3] = exp2f(sacc[j][3] - mn1);
            sum0 += sacc[j][0] + sacc[j][1];
            sum1 += sacc[j][2] + sacc[j][3];
        }
        sum0 += __shfl_xor_sync(0xffffffff, sum0, 1);
        sum0 += __shfl_xor_sync(0xffffffff, sum0, 2);
        sum1 += __shfl_xor_sync(0xffffffff, sum1, 1);
        sum1 += __shfl_xor_sync(0xffffffff, sum1, 2);
        l0 = l0 * corr0 + sum0;
        l1 = l1 * corr1 + sum1;
        m0 = mn0; m1 = mn1;
#pragma unroll
        for (int j = 0; j < 8; j++) {
            oacc[j][0] *= corr0; oacc[j][1] *= corr0;
            oacc[j][2] *= corr1; oacc[j][3] *= corr1;
        }

        uint32_t pa[4][4];
#pragma unroll
        for (int k = 0; k < 4; k++) {
            pa[k][0] = pack_f16(sacc[2 * k][0], sacc[2 * k][1]);
            pa[k][1] = pack_f16(sacc[2 * k][2], sacc[2 * k][3]);
            pa[k][2] = pack_f16(sacc[2 * k + 1][0], sacc[2 * k + 1][1]);
            pa[k][3] = pack_f16(sacc[2 * k + 1][2], sacc[2 * k + 1][3]);
        }

#pragma unroll
        for (int ks = 0; ks < 4; ks++) {
            uint32_t vb[8][2];
#pragma unroll
            for (int nt = 0; nt < 4; nt++) {
                const uint32_t off =
                    (uint32_t)((nt * 16 + (lid & 7) + ((lid & 16) ? 8 : 0)) * 128 +
                               (ks * 16 + ((lid & 8) ? 8 : 0)) * 2);
                uint32_t r0, r1, r2, r3;
                ldsm_x4(r0, r1, r2, r3, vb_base + SW128(off));
                vb[nt * 2][0] = r0; vb[nt * 2][1] = r1;
                vb[nt * 2 + 1][0] = r2; vb[nt * 2 + 1][1] = r3;
            }
#pragma unroll
            for (int j = 0; j < 8; j++) mma_f16(oacc[j], pa[ks], vb[j]);
        }
        __syncthreads();
    }

    const float inv0 = 1.f / l0, inv1 = 1.f / l1;
    const int qr0 = i0 + w * 16 + (lid >> 2);
    const size_t rb0 = (size_t)(bb * TFULL + qr0) * DM + h * 64;
    const size_t rb1 = rb0 + (size_t)8 * DM;
#pragma unroll
    for (int j = 0; j < 8; j++) {
        const int col = j * 8 + 2 * (lid & 3);
        *(uint32_t*)(O16 + rb0 + col) = pack_f16(oacc[j][0] * inv0, oacc[j][1] * inv0);
        *(uint32_t*)(O16 + rb1 + col) = pack_f16(oacc[j][2] * inv1, oacc[j][3] * inv1);
    }
#undef ISSUE_KV
}

// ===========================================================================
extern "C" void kernel_launch(void* const* d_in, const int* in_sizes, int n_in,
                              void* d_out, int out_size) {
    const float* x  = (const float*)d_in[0];
    const float* WQ = (const float*)d_in[1];
    const float* WK = (const float*)d_in[2];
    const float* WV = (const float*)d_in[3];
    const float* WO = (const float*)d_in[4];
    const int* tpos = (const int*)d_in[5];

    __half *x16, *wc16, *wo16, *att16, *q16, *k16, *v16t;
    cudaGetSymbolAddress((void**)&x16, g_x16);
    cudaGetSymbolAddress((void**)&wc16, g_wc16);
    cudaGetSymbolAddress((void**)&wo16, g_wo16);
    cudaGetSymbolAddress((void**)&att16, g_att16);
    cudaGetSymbolAddress((void**)&q16, g_q16);
    cudaGetSymbolAddress((void**)&k16, g_k16);
    cudaGetSymbolAddress((void**)&v16t, g_v16t);

    cudaFuncSetAttribute(gemm_qkv, cudaFuncAttributeMaxDynamicSharedMemorySize,
                         SM_GEMM);
    cudaFuncSetAttribute(gemm_f16, cudaFuncAttributeMaxDynamicSharedMemorySize,
                         SM_GEMM);

    convert_all<<<6656, 256>>>((const float4*)x, (const float4*)WQ, (const float4*)WK,
                               (const float4*)WV, (const float4*)WO,
                               x16, wc16, wo16);

    // QKV projection + fused RoPE + fp16 staging
    gemm_qkv<<<dim3(12, 32), 256, SM_GEMM>>>(x16, wc16, tpos, q16, k16, v16t);

    // Flash attention
    attn_mma<<<dim3(TFULL / 64, 16, 2), 128>>>(q16, k16, v16t, att16);

    // Output projection straight into d_out
    gemm_f16<<<dim3(8, 32), 256, SM_GEMM>>>(att16, wo16, (float*)d_out, DM);
}

// round 14
// speedup vs baseline: 1.4289x; 1.4289x over previous
#include <cuda_runtime.h>
#include <cuda_bf16.h>
#include <cuda_fp16.h>
#include <math.h>
#include <stdint.h>

#define TFULL 2048
#define DM    1024
#define LDQKV 1536   // [Q(1024) | K(256) | V(256)]

// Scratch (static device globals — no allocation allowed)
__device__ float  g_qkv[2 * TFULL * LDQKV];    // fp32 QKV projections
__device__ __half g_x16[2 * TFULL * DM];       // x fp16
__device__ __half g_wc16[1536 * 1024];         // concat WQ|WK|WV fp16
__device__ __half g_wo16[1024 * 1024];         // WO fp16
__device__ __half g_att16[2 * TFULL * DM];     // attn out fp16
__device__ __half g_q16[2 * 16 * TFULL * 64];  // [b][h][t][64]
__device__ __half g_k16[2 * 4 * TFULL * 64];   // [b][g][t][64]
__device__ __half g_v16t[2 * 4 * 64 * TFULL];  // [b][g][dim][t]

// ===========================================================================
// Helpers
// ===========================================================================
__device__ __forceinline__ uint32_t smem_u32(const void* p) {
    uint32_t a;
    asm("{ .reg .u64 t; cvta.to.shared.u64 t, %1; cvt.u32.u64 %0, t; }"
        : "=r"(a) : "l"(p));
    return a;
}
__device__ __forceinline__ void ldsm_x4(uint32_t& r0, uint32_t& r1, uint32_t& r2,
                                        uint32_t& r3, uint32_t addr) {
    asm volatile("ldmatrix.sync.aligned.m8n8.x4.shared.b16 {%0,%1,%2,%3}, [%4];"
                 : "=r"(r0), "=r"(r1), "=r"(r2), "=r"(r3) : "r"(addr));
}
__device__ __forceinline__ void mma_f16(float* c, const uint32_t* a, const uint32_t* b) {
    asm volatile(
        "mma.sync.aligned.m16n8k16.row.col.f32.f16.f16.f32 "
        "{%0,%1,%2,%3}, {%4,%5,%6,%7}, {%8,%9}, {%0,%1,%2,%3};"
        : "+f"(c[0]), "+f"(c[1]), "+f"(c[2]), "+f"(c[3])
        : "r"(a[0]), "r"(a[1]), "r"(a[2]), "r"(a[3]), "r"(b[0]), "r"(b[1]));
}
__device__ __forceinline__ uint32_t pack_f16(float a, float b) {
    uint32_t r;
    asm("cvt.rn.f16x2.f32 %0, %1, %2;" : "=r"(r) : "f"(b), "f"(a));
    return r;
}
__device__ __forceinline__ void cp16(uint32_t dst, const void* src) {
    asm volatile("cp.async.cg.shared.global [%0], [%1], 16;"
                 :: "r"(dst), "l"(src) : "memory");
}
#define CP_COMMIT() asm volatile("cp.async.commit_group;" ::: "memory")
#define CP_WAIT(n)  asm volatile("cp.async.wait_group %0;" :: "n"(n) : "memory")
#define SW128(off) ((off) ^ (((off) >> 3) & 0x70))

// ===========================================================================
// Fused convert: all fp32 sources -> fp16 in ONE launch.
// ===========================================================================
__global__ void convert_all(const float4* __restrict__ x, const float4* __restrict__ wq,
                            const float4* __restrict__ wk, const float4* __restrict__ wv,
                            const float4* __restrict__ wo,
                            __half* __restrict__ x16, __half* __restrict__ wc16,
                            __half* __restrict__ wo16) {
    const int i = blockIdx.x * 256 + threadIdx.x;
    const float4* src;
    __half* dst;
    size_t off;
    if (i < 1048576)      { src = x + i;               dst = x16;  off = (size_t)i * 4; }
    else if (i < 1310720) { const int j = i - 1048576; src = wq + j; dst = wc16; off = (size_t)j * 4; }
    else if (i < 1376256) { const int j = i - 1310720; src = wk + j; dst = wc16; off = 1048576 + (size_t)j * 4; }
    else if (i < 1441792) { const int j = i - 1376256; src = wv + j; dst = wc16; off = 1310720 + (size_t)j * 4; }
    else                  { const int j = i - 1441792; src = wo + j; dst = wo16; off = (size_t)j * 4; }
    const float4 v = *src;
    *(uint2*)(dst + off) = make_uint2(pack_f16(v.x, v.y), pack_f16(v.z, v.w));
}

// ===========================================================================
// Single-pass fp16 GEMM, cp.async 3-stage pipeline, 2 CTAs/SM.
// C[4096, N] = A[4096,1024] @ B[N,1024]^T. CTA tile 128x128, K-chunk 64.
// SMEM stage (32KB): A rows 0..127 x 128B (64 fp16) SW128; B at +16KB.
// ===========================================================================
#define GK 1024
#define SM_STAGE 32768
#define SM_GEMM (3 * SM_STAGE)

__global__ __launch_bounds__(256, 2)
void gemm_f16(const __half* __restrict__ A, const __half* __restrict__ B,
              float* __restrict__ C, int ldc) {
    extern __shared__ char sm[];
    const uint32_t smb = smem_u32(sm);
    const int tid = threadIdx.x;
    const int lid = tid & 31;
    const int wid = tid >> 5;
    const int wm = wid & 3;
    const int wn = wid >> 2;
    const int m0 = blockIdx.y * 128;
    const int n0 = blockIdx.x * 128;

#define ISSUE(c, stage)                                                        \
    {                                                                          \
        const int kc = (c) * 64;                                               \
        const uint32_t sbase = smb + (stage) * SM_STAGE;                       \
        _Pragma("unroll")                                                      \
        for (int u = 0; u < 4; u++) {                                          \
            const int idx = tid + 256 * u;                                     \
            const int row = idx >> 3, c8 = idx & 7;                            \
            const uint32_t doff = SW128((uint32_t)(row * 128 + c8 * 16));      \
            cp16(sbase + doff, A + (size_t)(m0 + row) * GK + kc + c8 * 8);     \
            cp16(sbase + 16384 + doff,                                         \
                 B + (size_t)(n0 + row) * GK + kc + c8 * 8);                   \
        }                                                                      \
        CP_COMMIT();                                                           \
    }

    float acc[2][8][4];
#pragma unroll
    for (int s = 0; s < 2; s++)
#pragma unroll
        for (int j = 0; j < 8; j++)
#pragma unroll
            for (int q = 0; q < 4; q++) acc[s][j][q] = 0.f;

    ISSUE(0, 0);
    ISSUE(1, 1);

    int stage = 0;
    for (int c = 0; c < 16; c++) {
        if (c == 15) { CP_WAIT(0); } else { CP_WAIT(1); }
        __syncthreads();
        if (c + 2 < 16) {
            const int ns = (stage + 2 >= 3) ? stage - 1 : stage + 2;
            ISSUE(c + 2, ns);
        }

        const uint32_t abase = smb + stage * SM_STAGE;
        const uint32_t bbase = abase + 16384;
#pragma unroll
        for (int kk = 0; kk < 4; kk++) {
            uint32_t ah[2][4];
#pragma unroll
            for (int sub = 0; sub < 2; sub++) {
                const uint32_t row = (uint32_t)(wm * 32 + sub * 16 + (lid & 15));
                const uint32_t col2 = (uint32_t)((kk * 16 + ((lid >> 4) << 3)) * 2);
                ldsm_x4(ah[sub][0], ah[sub][1], ah[sub][2], ah[sub][3],
                        abase + SW128(row * 128 + col2));
            }
#pragma unroll
            for (int nt = 0; nt < 4; nt++) {
                const uint32_t rown =
                    (uint32_t)(wn * 64 + nt * 16 + (lid & 7) + ((lid & 16) ? 8 : 0));
                const uint32_t colb = (uint32_t)((kk * 16 + ((lid & 8) ? 8 : 0)) * 2);
                uint32_t b[4];
                ldsm_x4(b[0], b[1], b[2], b[3], bbase + SW128(rown * 128 + colb));
#pragma unroll
                for (int sub = 0; sub < 2; sub++) {
                    mma_f16(acc[sub][2 * nt],     ah[sub], b);
                    mma_f16(acc[sub][2 * nt + 1], ah[sub], b + 2);
                }
            }
        }
        stage = (stage + 1 == 3) ? 0 : stage + 1;
    }

    const int tr = lid >> 2;
    const int tc = (lid & 3) * 2;
#pragma unroll
    for (int sub = 0; sub < 2; sub++) {
        const int m = m0 + wm * 32 + sub * 16 + tr;
#pragma unroll
        for (int j = 0; j < 8; j++) {
            const int n = n0 + wn * 64 + j * 8 + tc;
            *(float2*)(C + (size_t)m * ldc + n) =
                make_float2(acc[sub][j][0], acc[sub][j][1]);
            *(float2*)(C + (size_t)(m + 8) * ldc + n) =
                make_float2(acc[sub][j][2], acc[sub][j][3]);
        }
    }
#undef ISSUE
}

// ===========================================================================
// RoPE + fp16 emit
// ===========================================================================
#define QSCALE 0.18033688011112043f   // log2(e) / 8

__global__ void rope_fp16(const float* __restrict__ QKV, const int* __restrict__ tpos,
                          __half* __restrict__ Q16, __half* __restrict__ K16,
                          __half* __restrict__ V16t) {
    const int row = blockIdx.x;
    const int bb = row >> 11;
    const int t = row & (TFULL - 1);
    const float pos = (float)tpos[t];
    const float* rp = QKV + (size_t)row * LDQKV;
    const int tid = threadIdx.x;

    for (int p = tid; p < 512; p += 128) {
        const int head = p >> 5, pp = p & 31;
        const int c0 = head * 64 + 2 * pp;
        const float inv_freq = __expf(-0.28782313662425572f * (float)pp);
        const float ang = pos * inv_freq;
        float s, c;
        sincosf(ang, &s, &c);
        const float x1 = rp[c0], x2 = rp[c0 + 1];
        const float r1 = (x1 * c - x2 * s) * QSCALE;
        const float r2 = (x1 * s + x2 * c) * QSCALE;
        *(__half2*)(Q16 + ((size_t)((bb * 16 + head) * TFULL + t)) * 64 + 2 * pp) =
            __floats2half2_rn(r1, r2);
    }
    if (tid < 128) {
        const int g = tid >> 5, pp = tid & 31;
        const int c0 = 1024 + g * 64 + 2 * pp;
        const float inv_freq = __expf(-0.28782313662425572f * (float)pp);
        const float ang = pos * inv_freq;
        float s, c;
        sincosf(ang, &s, &c);
        const float x1 = rp[c0], x2 = rp[c0 + 1];
        *(__half2*)(K16 + ((size_t)((bb * 4 + g) * TFULL + t)) * 64 + 2 * pp) =
            __floats2half2_rn(x1 * c - x2 * s, x1 * s + x2 * c);
    }
    for (int e = tid; e < 256; e += 128) {
        const int g = e >> 6, d = e & 63;
        V16t[((size_t)((bb * 4 + g) * 64 + d)) * TFULL + t] =
            __float2half(rp[1280 + e]);
    }
}

// ===========================================================================
// fp16 mma flash attention, cp.async double-buffered K/V -> fp16 output.
// __launch_bounds__(128, 4): cap regs at 128 so 4 CTAs (16 warps) fit per SM.
// ===========================================================================
__global__ __launch_bounds__(128, 4)
void attn_mma(const __half* __restrict__ Q16, const __half* __restrict__ K16,
              const __half* __restrict__ V16t, __half* __restrict__ O16) {
    __shared__ __align__(1024) char smQ[8192];
    __shared__ __align__(1024) char smK[2][8192];
    __shared__ __align__(1024) char smV[2][8192];
    const int tid = threadIdx.x, lid = tid & 31, w = tid >> 5;
    const int i0 = blockIdx.x * 64;
    const int h = blockIdx.y, bb = blockIdx.z, g = h >> 2;

    const uint32_t smbQ = smem_u32(smQ);
    const uint32_t smbK = smem_u32(smK);
    const uint32_t smbV = smem_u32(smV);
    const __half* kgb = K16 + ((size_t)((bb * 4 + g) * TFULL)) * 64;
    const __half* vgb = V16t + ((size_t)((bb * 4 + g) * 64)) * TFULL;
    const int j0 = (i0 - 512 > 0) ? (i0 - 512) : 0;
    const int nchunks = (i0 - j0) / 64 + 1;

#define ISSUE_KV(jc, buf)                                                      \
    {                                                                          \
        _Pragma("unroll")                                                      \
        for (int u = 0; u < 4; u++) {                                          \
            const int idx = tid + 128 * u;                                     \
            const int r = idx >> 3, cc = idx & 7;                              \
            const uint32_t d = (uint32_t)(buf) * 8192 +                        \
                               SW128((uint32_t)(r * 128 + cc * 16));           \
            cp16(smbK + d, kgb + (size_t)((jc) + r) * 64 + cc * 8);            \
            cp16(smbV + d, vgb + (size_t)r * TFULL + (jc) + cc * 8);           \
        }                                                                      \
        CP_COMMIT();                                                           \
    }

    ISSUE_KV(j0, 0);
    const __half* qg = Q16 + ((size_t)((bb * 16 + h) * TFULL + i0)) * 64;
#pragma unroll
    for (int u = 0; u < 4; u++) {
        const int idx = tid + 128 * u;
        const int r = idx >> 3, c = idx & 7;
        *(uint4*)(smQ + SW128((uint32_t)(r * 128 + c * 16))) =
            *(const uint4*)(qg + (size_t)r * 64 + c * 8);
    }
    __syncthreads();

    uint32_t qa[4][4];
#pragma unroll
    for (int ks = 0; ks < 4; ks++) {
        const uint32_t off =
            (uint32_t)((w * 16 + (lid & 15)) * 128 + (ks * 16 + ((lid >> 4) << 3)) * 2);
        ldsm_x4(qa[ks][0], qa[ks][1], qa[ks][2], qa[ks][3], smbQ + SW128(off));
    }

    float oacc[8][4];
#pragma unroll
    for (int j = 0; j < 8; j++)
#pragma unroll
        for (int q = 0; q < 4; q++) oacc[j][q] = 0.f;
    float m0 = -1e30f, m1 = -1e30f, l0 = 0.f, l1 = 0.f;

    for (int ci = 0; ci < nchunks; ci++) {
        const int jc = j0 + ci * 64;
        const int buf = ci & 1;
        if (ci + 1 < nchunks) {
            ISSUE_KV(jc + 64, buf ^ 1);
            CP_WAIT(1);
        } else {
            CP_WAIT(0);
        }
        __syncthreads();

        const uint32_t kb_base = smbK + buf * 8192;
        const uint32_t vb_base = smbV + buf * 8192;

        float sacc[8][4];
#pragma unroll
        for (int j = 0; j < 8; j++)
#pragma unroll
            for (int q = 0; q < 4; q++) sacc[j][q] = 0.f;
#pragma unroll
        for (int ks = 0; ks < 4; ks++) {
            uint32_t kb[8][2];
#pragma unroll
            for (int nt = 0; nt < 4; nt++) {
                const uint32_t off =
                    (uint32_t)((nt * 16 + (lid & 7) + ((lid & 16) ? 8 : 0)) * 128 +
                               (ks * 16 + ((lid & 8) ? 8 : 0)) * 2);
                uint32_t r0, r1, r2, r3;
                ldsm_x4(r0, r1, r2, r3, kb_base + SW128(off));
                kb[nt * 2][0] = r0; kb[nt * 2][1] = r1;
                kb[nt * 2 + 1][0] = r2; kb[nt * 2 + 1][1] = r3;
            }
#pragma unroll
            for (int j = 0; j < 8; j++) mma_f16(sacc[j], qa[ks], kb[j]);
        }

        if (jc == i0 || i0 - jc == 512) {
            const int r0 = i0 + w * 16 + (lid >> 2), r1 = r0 + 8;
#pragma unroll
            for (int j = 0; j < 8; j++) {
                const int c0 = jc + j * 8 + 2 * (lid & 3);
                if (c0 > r0 || r0 - c0 > 512)         sacc[j][0] = -1e30f;
                if (c0 + 1 > r0 || r0 - c0 - 1 > 512) sacc[j][1] = -1e30f;
                if (c0 > r1 || r1 - c0 > 512)         sacc[j][2] = -1e30f;
                if (c0 + 1 > r1 || r1 - c0 - 1 > 512) sacc[j][3] = -1e30f;
            }
        }

        float mx0 = -1e30f, mx1 = -1e30f;
#pragma unroll
        for (int j = 0; j < 8; j++) {
            mx0 = fmaxf(mx0, fmaxf(sacc[j][0], sacc[j][1]));
            mx1 = fmaxf(mx1, fmaxf(sacc[j][2], sacc[j][3]));
        }
        mx0 = fmaxf(mx0, __shfl_xor_sync(0xffffffff, mx0, 1));
        mx0 = fmaxf(mx0, __shfl_xor_sync(0xffffffff, mx0, 2));
        mx1 = fmaxf(mx1, __shfl_xor_sync(0xffffffff, mx1, 1));
        mx1 = fmaxf(mx1, __shfl_xor_sync(0xffffffff, mx1, 2));
        const float mn0 = fmaxf(m0, mx0), mn1 = fmaxf(m1, mx1);
        const float corr0 = exp2f(m0 - mn0), corr1 = exp2f(m1 - mn1);
        float sum0 = 0.f, sum1 = 0.f;
#pragma unroll
        for (int j = 0; j < 8; j++) {
            sacc[j][0] = exp2f(sacc[j][0] - mn0);
            sacc[j][1] = exp2f(sacc[j][1] - mn0);
            sacc[j][2] = exp2f(sacc[j][2] - mn1);
            sacc[j][3] = exp2f(sacc[j][3] - mn1);
            sum0 += sacc[j][0] + sacc[j][1];
            sum1 += sacc[j][2] + sacc[j][3];
        }
        sum0 += __shfl_xor_sync(0xffffffff, sum0, 1);
        sum0 += __shfl_xor_sync(0xffffffff, sum0, 2);
        sum1 += __shfl_xor_sync(0xffffffff, sum1, 1);
        sum1 += __shfl_xor_sync(0xffffffff, sum1, 2);
        l0 = l0 * corr0 + sum0;
        l1 = l1 * corr1 + sum1;
        m0 = mn0; m1 = mn1;
#pragma unroll
        for (int j = 0; j < 8; j++) {
            oacc[j][0] *= corr0; oacc[j][1] *= corr0;
            oacc[j][2] *= corr1; oacc[j][3] *= corr1;
        }

        uint32_t pa[4][4];
#pragma unroll
        for (int k = 0; k < 4; k++) {
            pa[k][0] = pack_f16(sacc[2 * k][0], sacc[2 * k][1]);
            pa[k][1] = pack_f16(sacc[2 * k][2], sacc[2 * k][3]);
            pa[k][2] = pack_f16(sacc[2 * k + 1][0], sacc[2 * k + 1][1]);
            pa[k][3] = pack_f16(sacc[2 * k + 1][2], sacc[2 * k + 1][3]);
        }

#pragma unroll
        for (int ks = 0; ks < 4; ks++) {
            uint32_t vb[8][2];
#pragma unroll
            for (int nt = 0; nt < 4; nt++) {
                const uint32_t off =
                    (uint32_t)((nt * 16 + (lid & 7) + ((lid & 16) ? 8 : 0)) * 128 +
                               (ks * 16 + ((lid & 8) ? 8 : 0)) * 2);
                uint32_t r0, r1, r2, r3;
                ldsm_x4(r0, r1, r2, r3, vb_base + SW128(off));
                vb[nt * 2][0] = r0; vb[nt * 2][1] = r1;
                vb[nt * 2 + 1][0] = r2; vb[nt * 2 + 1][1] = r3;
            }
#pragma unroll
            for (int j = 0; j < 8; j++) mma_f16(oacc[j], pa[ks], vb[j]);
        }
        __syncthreads();
    }

    const float inv0 = 1.f / l0, inv1 = 1.f / l1;
    const int qr0 = i0 + w * 16 + (lid >> 2);
    const size_t rb0 = (size_t)(bb * TFULL + qr0) * DM + h * 64;
    const size_t rb1 = rb0 + (size_t)8 * DM;
#pragma unroll
    for (int j = 0; j < 8; j++) {
        const int col = j * 8 + 2 * (lid & 3);
        *(uint32_t*)(O16 + rb0 + col) = pack_f16(oacc[j][0] * inv0, oacc[j][1] * inv0);
        *(uint32_t*)(O16 + rb1 + col) = pack_f16(oacc[j][2] * inv1, oacc[j][3] * inv1);
    }
#undef ISSUE_KV
}

// ===========================================================================
extern "C" void kernel_launch(void* const* d_in, const int* in_sizes, int n_in,
                              void* d_out, int out_size) {
    const float* x  = (const float*)d_in[0];
    const float* WQ = (const float*)d_in[1];
    const float* WK = (const float*)d_in[2];
    const float* WV = (const float*)d_in[3];
    const float* WO = (const float*)d_in[4];
    const int* tpos = (const int*)d_in[5];

    float* qkv;
    __half *x16, *wc16, *wo16, *att16, *q16, *k16, *v16t;
    cudaGetSymbolAddress((void**)&qkv, g_qkv);
    cudaGetSymbolAddress((void**)&x16, g_x16);
    cudaGetSymbolAddress((void**)&wc16, g_wc16);
    cudaGetSymbolAddress((void**)&wo16, g_wo16);
    cudaGetSymbolAddress((void**)&att16, g_att16);
    cudaGetSymbolAddress((void**)&q16, g_q16);
    cudaGetSymbolAddress((void**)&k16, g_k16);
    cudaGetSymbolAddress((void**)&v16t, g_v16t);

    cudaFuncSetAttribute(gemm_f16, cudaFuncAttributeMaxDynamicSharedMemorySize,
                         SM_GEMM);

    convert_all<<<6656, 256>>>((const float4*)x, (const float4*)WQ, (const float4*)WK,
                               (const float4*)WV, (const float4*)WO,
                               x16, wc16, wo16);

    // QKV projection: [4096,1536] = x @ Wcat^T, ldc=1536
    gemm_f16<<<dim3(12, 32), 256, SM_GEMM>>>(x16, wc16, qkv, LDQKV);

    rope_fp16<<<2 * TFULL, 128>>>(qkv, tpos, q16, k16, v16t);

    attn_mma<<<dim3(TFULL / 64, 16, 2), 128>>>(q16, k16, v16t, att16);

    // Output projection straight into d_out
    gemm_f16<<<dim3(8, 32), 256, SM_GEMM>>>(att16, wo16, (float*)d_out, DM);
}

// round 15
// speedup vs baseline: 1.4356x; 1.0047x over previous
#include <cuda_runtime.h>
#include <cuda_bf16.h>
#include <cuda_fp16.h>
#include <math.h>
#include <stdint.h>

#define TFULL 2048
#define DM    1024
#define LDQKV 1536   // [Q(1024) | K(256) | V(256)]

// Scratch (static device globals — no allocation allowed)
__device__ float  g_qkv[2 * TFULL * LDQKV];    // fp32 QKV projections
__device__ __half g_x16[2 * TFULL * DM];       // x fp16
__device__ __half g_wc16[1536 * 1024];         // concat WQ|WK|WV fp16
__device__ __half g_wo16[1024 * 1024];         // WO fp16
__device__ __half g_att16[2 * TFULL * DM];     // attn out fp16
__device__ __half g_q16[2 * 16 * TFULL * 64];  // [b][h][t][64]
__device__ __half g_k16[2 * 4 * TFULL * 64];   // [b][g][t][64]
__device__ __half g_v16t[2 * 4 * 64 * TFULL];  // [b][g][dim][t]

// ===========================================================================
// Helpers
// ===========================================================================
__device__ __forceinline__ uint32_t smem_u32(const void* p) {
    uint32_t a;
    asm("{ .reg .u64 t; cvta.to.shared.u64 t, %1; cvt.u32.u64 %0, t; }"
        : "=r"(a) : "l"(p));
    return a;
}
__device__ __forceinline__ void ldsm_x4(uint32_t& r0, uint32_t& r1, uint32_t& r2,
                                        uint32_t& r3, uint32_t addr) {
    asm volatile("ldmatrix.sync.aligned.m8n8.x4.shared.b16 {%0,%1,%2,%3}, [%4];"
                 : "=r"(r0), "=r"(r1), "=r"(r2), "=r"(r3) : "r"(addr));
}
__device__ __forceinline__ void mma_f16(float* c, const uint32_t* a, const uint32_t* b) {
    asm volatile(
        "mma.sync.aligned.m16n8k16.row.col.f32.f16.f16.f32 "
        "{%0,%1,%2,%3}, {%4,%5,%6,%7}, {%8,%9}, {%0,%1,%2,%3};"
        : "+f"(c[0]), "+f"(c[1]), "+f"(c[2]), "+f"(c[3])
        : "r"(a[0]), "r"(a[1]), "r"(a[2]), "r"(a[3]), "r"(b[0]), "r"(b[1]));
}
__device__ __forceinline__ uint32_t pack_f16(float a, float b) {
    uint32_t r;
    asm("cvt.rn.f16x2.f32 %0, %1, %2;" : "=r"(r) : "f"(b), "f"(a));
    return r;
}
__device__ __forceinline__ void cp16(uint32_t dst, const void* src) {
    asm volatile("cp.async.cg.shared.global [%0], [%1], 16;"
                 :: "r"(dst), "l"(src) : "memory");
}
#define CP_COMMIT() asm volatile("cp.async.commit_group;" ::: "memory")
#define CP_WAIT(n)  asm volatile("cp.async.wait_group %0;" :: "n"(n) : "memory")
#define SW128(off) ((off) ^ (((off) >> 3) & 0x70))

// ===========================================================================
// Fused convert: all fp32 sources -> fp16 in ONE launch.
// ===========================================================================
__global__ void convert_all(const float4* __restrict__ x, const float4* __restrict__ wq,
                            const float4* __restrict__ wk, const float4* __restrict__ wv,
                            const float4* __restrict__ wo,
                            __half* __restrict__ x16, __half* __restrict__ wc16,
                            __half* __restrict__ wo16) {
    const int i = blockIdx.x * 256 + threadIdx.x;
    const float4* src;
    __half* dst;
    size_t off;
    if (i < 1048576)      { src = x + i;               dst = x16;  off = (size_t)i * 4; }
    else if (i < 1310720) { const int j = i - 1048576; src = wq + j; dst = wc16; off = (size_t)j * 4; }
    else if (i < 1376256) { const int j = i - 1310720; src = wk + j; dst = wc16; off = 1048576 + (size_t)j * 4; }
    else if (i < 1441792) { const int j = i - 1376256; src = wv + j; dst = wc16; off = 1310720 + (size_t)j * 4; }
    else                  { const int j = i - 1441792; src = wo + j; dst = wo16; off = (size_t)j * 4; }
    const float4 v = *src;
    *(uint2*)(dst + off) = make_uint2(pack_f16(v.x, v.y), pack_f16(v.z, v.w));
}

// ===========================================================================
// Single-pass fp16 GEMM, cp.async 3-stage pipeline, 2 CTAs/SM.
// Fragment double-buffering: load kk+1 frags while issuing kk's mmas.
// C[4096, N] = A[4096,1024] @ B[N,1024]^T. CTA tile 128x128, K-chunk 64.
// ===========================================================================
#define GK 1024
#define SM_STAGE 32768
#define SM_GEMM (3 * SM_STAGE)

__global__ __launch_bounds__(256, 2)
void gemm_f16(const __half* __restrict__ A, const __half* __restrict__ B,
              float* __restrict__ C, int ldc) {
    extern __shared__ char sm[];
    const uint32_t smb = smem_u32(sm);
    const int tid = threadIdx.x;
    const int lid = tid & 31;
    const int wid = tid >> 5;
    const int wm = wid & 3;
    const int wn = wid >> 2;
    const int m0 = blockIdx.y * 128;
    const int n0 = blockIdx.x * 128;

#define ISSUE(c, stage)                                                        \
    {                                                                          \
        const int kc = (c) * 64;                                               \
        const uint32_t sbase = smb + (stage) * SM_STAGE;                       \
        _Pragma("unroll")                                                      \
        for (int u = 0; u < 4; u++) {                                          \
            const int idx = tid + 256 * u;                                     \
            const int row = idx >> 3, c8 = idx & 7;                            \
            const uint32_t doff = SW128((uint32_t)(row * 128 + c8 * 16));      \
            cp16(sbase + doff, A + (size_t)(m0 + row) * GK + kc + c8 * 8);     \
            cp16(sbase + 16384 + doff,                                         \
                 B + (size_t)(n0 + row) * GK + kc + c8 * 8);                   \
        }                                                                      \
        CP_COMMIT();                                                           \
    }

// Load all A/B fragments for K-subchunk kk into register buffer `buf`
#define LOAD_FRAGS(kk, buf)                                                    \
    {                                                                          \
        _Pragma("unroll")                                                      \
        for (int sub = 0; sub < 2; sub++) {                                    \
            const uint32_t row = (uint32_t)(wm * 32 + sub * 16 + (lid & 15));  \
            const uint32_t col2 = (uint32_t)(((kk) * 16 + ((lid >> 4) << 3)) * 2); \
            ldsm_x4(ah[buf][sub][0], ah[buf][sub][1], ah[buf][sub][2],         \
                    ah[buf][sub][3], abase + SW128(row * 128 + col2));         \
        }                                                                      \
        _Pragma("unroll")                                                      \
        for (int nt = 0; nt < 4; nt++) {                                       \
            const uint32_t rown =                                              \
                (uint32_t)(wn * 64 + nt * 16 + (lid & 7) + ((lid & 16) ? 8 : 0)); \
            const uint32_t colb = (uint32_t)(((kk) * 16 + ((lid & 8) ? 8 : 0)) * 2); \
            ldsm_x4(bf[buf][nt * 2][0], bf[buf][nt * 2][1],                    \
                    bf[buf][nt * 2 + 1][0], bf[buf][nt * 2 + 1][1],            \
                    bbase + SW128(rown * 128 + colb));                         \
        }                                                                      \
    }

    float acc[2][8][4];
#pragma unroll
    for (int s = 0; s < 2; s++)
#pragma unroll
        for (int j = 0; j < 8; j++)
#pragma unroll
            for (int q = 0; q < 4; q++) acc[s][j][q] = 0.f;

    ISSUE(0, 0);
    ISSUE(1, 1);

    uint32_t ah[2][2][4], bf[2][8][2];

    int stage = 0;
    for (int c = 0; c < 16; c++) {
        if (c == 15) { CP_WAIT(0); } else { CP_WAIT(1); }
        __syncthreads();
        if (c + 2 < 16) {
            const int ns = (stage + 2 >= 3) ? stage - 1 : stage + 2;
            ISSUE(c + 2, ns);
        }

        const uint32_t abase = smb + stage * SM_STAGE;
        const uint32_t bbase = abase + 16384;

        LOAD_FRAGS(0, 0);
#pragma unroll
        for (int kk = 0; kk < 4; kk++) {
            const int cur = kk & 1;
            if (kk < 3) LOAD_FRAGS(kk + 1, cur ^ 1);
#pragma unroll
            for (int j = 0; j < 8; j++) {
                mma_f16(acc[0][j], ah[cur][0], bf[cur][j]);
                mma_f16(acc[1][j], ah[cur][1], bf[cur][j]);
            }
        }
        stage = (stage + 1 == 3) ? 0 : stage + 1;
    }

    const int tr = lid >> 2;
    const int tc = (lid & 3) * 2;
#pragma unroll
    for (int sub = 0; sub < 2; sub++) {
        const int m = m0 + wm * 32 + sub * 16 + tr;
#pragma unroll
        for (int j = 0; j < 8; j++) {
            const int n = n0 + wn * 64 + j * 8 + tc;
            *(float2*)(C + (size_t)m * ldc + n) =
                make_float2(acc[sub][j][0], acc[sub][j][1]);
            *(float2*)(C + (size_t)(m + 8) * ldc + n) =
                make_float2(acc[sub][j][2], acc[sub][j][3]);
        }
    }
#undef ISSUE
#undef LOAD_FRAGS
}

// ===========================================================================
// RoPE + fp16 emit
// ===========================================================================
#define QSCALE 0.18033688011112043f   // log2(e) / 8

__global__ void rope_fp16(const float* __restrict__ QKV, const int* __restrict__ tpos,
                          __half* __restrict__ Q16, __half* __restrict__ K16,
                          __half* __restrict__ V16t) {
    const int row = blockIdx.x;
    const int bb = row >> 11;
    const int t = row & (TFULL - 1);
    const float pos = (float)tpos[t];
    const float* rp = QKV + (size_t)row * LDQKV;
    const int tid = threadIdx.x;

    for (int p = tid; p < 512; p += 128) {
        const int head = p >> 5, pp = p & 31;
        const int c0 = head * 64 + 2 * pp;
        const float inv_freq = __expf(-0.28782313662425572f * (float)pp);
        const float ang = pos * inv_freq;
        float s, c;
        sincosf(ang, &s, &c);
        const float x1 = rp[c0], x2 = rp[c0 + 1];
        const float r1 = (x1 * c - x2 * s) * QSCALE;
        const float r2 = (x1 * s + x2 * c) * QSCALE;
        *(__half2*)(Q16 + ((size_t)((bb * 16 + head) * TFULL + t)) * 64 + 2 * pp) =
            __floats2half2_rn(r1, r2);
    }
    if (tid < 128) {
        const int g = tid >> 5, pp = tid & 31;
        const int c0 = 1024 + g * 64 + 2 * pp;
        const float inv_freq = __expf(-0.28782313662425572f * (float)pp);
        const float ang = pos * inv_freq;
        float s, c;
        sincosf(ang, &s, &c);
        const float x1 = rp[c0], x2 = rp[c0 + 1];
        *(__half2*)(K16 + ((size_t)((bb * 4 + g) * TFULL + t)) * 64 + 2 * pp) =
            __floats2half2_rn(x1 * c - x2 * s, x1 * s + x2 * c);
    }
    for (int e = tid; e < 256; e += 128) {
        const int g = e >> 6, d = e & 63;
        V16t[((size_t)((bb * 4 + g) * 64 + d)) * TFULL + t] =
            __float2half(rp[1280 + e]);
    }
}

// ===========================================================================
// fp16 mma flash attention, cp.async double-buffered K/V -> fp16 output.
// __launch_bounds__(128, 4): 4 CTAs (16 warps) per SM.
// ===========================================================================
__global__ __launch_bounds__(128, 4)
void attn_mma(const __half* __restrict__ Q16, const __half* __restrict__ K16,
              const __half* __restrict__ V16t, __half* __restrict__ O16) {
    __shared__ __align__(1024) char smQ[8192];
    __shared__ __align__(1024) char smK[2][8192];
    __shared__ __align__(1024) char smV[2][8192];
    const int tid = threadIdx.x, lid = tid & 31, w = tid >> 5;
    const int i0 = blockIdx.x * 64;
    const int h = blockIdx.y, bb = blockIdx.z, g = h >> 2;

    const uint32_t smbQ = smem_u32(smQ);
    const uint32_t smbK = smem_u32(smK);
    const uint32_t smbV = smem_u32(smV);
    const __half* kgb = K16 + ((size_t)((bb * 4 + g) * TFULL)) * 64;
    const __half* vgb = V16t + ((size_t)((bb * 4 + g) * 64)) * TFULL;
    const int j0 = (i0 - 512 > 0) ? (i0 - 512) : 0;
    const int nchunks = (i0 - j0) / 64 + 1;

#define ISSUE_KV(jc, buf)                                                      \
    {                                                                          \
        _Pragma("unroll")                                                      \
        for (int u = 0; u < 4; u++) {                                          \
            const int idx = tid + 128 * u;                                     \
            const int r = idx >> 3, cc = idx & 7;                              \
            const uint32_t d = (uint32_t)(buf) * 8192 +                        \
                               SW128((uint32_t)(r * 128 + cc * 16));           \
            cp16(smbK + d, kgb + (size_t)((jc) + r) * 64 + cc * 8);            \
            cp16(smbV + d, vgb + (size_t)r * TFULL + (jc) + cc * 8);           \
        }                                                                      \
        CP_COMMIT();                                                           \
    }

    ISSUE_KV(j0, 0);
    const __half* qg = Q16 + ((size_t)((bb * 16 + h) * TFULL + i0)) * 64;
#pragma unroll
    for (int u = 0; u < 4; u++) {
        const int idx = tid + 128 * u;
        const int r = idx >> 3, c = idx & 7;
        *(uint4*)(smQ + SW128((uint32_t)(r * 128 + c * 16))) =
            *(const uint4*)(qg + (size_t)r * 64 + c * 8);
    }
    __syncthreads();

    uint32_t qa[4][4];
#pragma unroll
    for (int ks = 0; ks < 4; ks++) {
        const uint32_t off =
            (uint32_t)((w * 16 + (lid & 15)) * 128 + (ks * 16 + ((lid >> 4) << 3)) * 2);
        ldsm_x4(qa[ks][0], qa[ks][1], qa[ks][2], qa[ks][3], smbQ + SW128(off));
    }

    float oacc[8][4];
#pragma unroll
    for (int j = 0; j < 8; j++)
#pragma unroll
        for (int q = 0; q < 4; q++) oacc[j][q] = 0.f;
    float m0 = -1e30f, m1 = -1e30f, l0 = 0.f, l1 = 0.f;

    for (int ci = 0; ci < nchunks; ci++) {
        const int jc = j0 + ci * 64;
        const int buf = ci & 1;
        if (ci + 1 < nchunks) {
            ISSUE_KV(jc + 64, buf ^ 1);
            CP_WAIT(1);
        } else {
            CP_WAIT(0);
        }
        __syncthreads();

        const uint32_t kb_base = smbK + buf * 8192;
        const uint32_t vb_base = smbV + buf * 8192;

        float sacc[8][4];
#pragma unroll
        for (int j = 0; j < 8; j++)
#pragma unroll
            for (int q = 0; q < 4; q++) sacc[j][q] = 0.f;
#pragma unroll
        for (int ks = 0; ks < 4; ks++) {
            uint32_t kb[8][2];
#pragma unroll
            for (int nt = 0; nt < 4; nt++) {
                const uint32_t off =
                    (uint32_t)((nt * 16 + (lid & 7) + ((lid & 16) ? 8 : 0)) * 128 +
                               (ks * 16 + ((lid & 8) ? 8 : 0)) * 2);
                uint32_t r0, r1, r2, r3;
                ldsm_x4(r0, r1, r2, r3, kb_base + SW128(off));
                kb[nt * 2][0] = r0; kb[nt * 2][1] = r1;
                kb[nt * 2 + 1][0] = r2; kb[nt * 2 + 1][1] = r3;
            }
#pragma unroll
            for (int j = 0; j < 8; j++) mma_f16(sacc[j], qa[ks], kb[j]);
        }

        if (jc == i0 || i0 - jc == 512) {
            const int r0 = i0 + w * 16 + (lid >> 2), r1 = r0 + 8;
#pragma unroll
            for (int j = 0; j < 8; j++) {
                const int c0 = jc + j * 8 + 2 * (lid & 3);
                if (c0 > r0 || r0 - c0 > 512)         sacc[j][0] = -1e30f;
                if (c0 + 1 > r0 || r0 - c0 - 1 > 512) sacc[j][1] = -1e30f;
                if (c0 > r1 || r1 - c0 > 512)         sacc[j][2] = -1e30f;
                if (c0 + 1 > r1 || r1 - c0 - 1 > 512) sacc[j][3] = -1e30f;
            }
        }

        float mx0 = -1e30f, mx1 = -1e30f;
#pragma unroll
        for (int j = 0; j < 8; j++) {
            mx0 = fmaxf(mx0, fmaxf(sacc[j][0], sacc[j][1]));
            mx1 = fmaxf(mx1, fmaxf(sacc[j][2], sacc[j][3]));
        }
        mx0 = fmaxf(mx0, __shfl_xor_sync(0xffffffff, mx0, 1));
        mx0 = fmaxf(mx0, __shfl_xor_sync(0xffffffff, mx0, 2));
        mx1 = fmaxf(mx1, __shfl_xor_sync(0xffffffff, mx1, 1));
        mx1 = fmaxf(mx1, __shfl_xor_sync(0xffffffff, mx1, 2));
        const float mn0 = fmaxf(m0, mx0), mn1 = fmaxf(m1, mx1);
        const float corr0 = exp2f(m0 - mn0), corr1 = exp2f(m1 - mn1);
        float sum0 = 0.f, sum1 = 0.f;
#pragma unroll
        for (int j = 0; j < 8; j++) {
            sacc[j][0] = exp2f(sacc[j][0] - mn0);
            sacc[j][1] = exp2f(sacc[j][1] - mn0);
            sacc[j][2] = exp2f(sacc[j][2] - mn1);
            sacc[j][3] = exp2f(sacc[j][3] - mn1);
            sum0 += sacc[j][0] + sacc[j][1];
            sum1 += sacc[j][2] + sacc[j][3];
        }
        sum0 += __shfl_xor_sync(0xffffffff, sum0, 1);
        sum0 += __shfl_xor_sync(0xffffffff, sum0, 2);
        sum1 += __shfl_xor_sync(0xffffffff, sum1, 1);
        sum1 += __shfl_xor_sync(0xffffffff, sum1, 2);
        l0 = l0 * corr0 + sum0;
        l1 = l1 * corr1 + sum1;
        m0 = mn0; m1 = mn1;
#pragma unroll
        for (int j = 0; j < 8; j++) {
            oacc[j][0] *= corr0; oacc[j][1] *= corr0;
            oacc[j][2] *= corr1; oacc[j][3] *= corr1;
        }

        uint32_t pa[4][4];
#pragma unroll
        for (int k = 0; k < 4; k++) {
            pa[k][0] = pack_f16(sacc[2 * k][0], sacc[2 * k][1]);
            pa[k][1] = pack_f16(sacc[2 * k][2], sacc[2 * k][3]);
            pa[k][2] = pack_f16(sacc[2 * k + 1][0], sacc[2 * k + 1][1]);
            pa[k][3] = pack_f16(sacc[2 * k + 1][2], sacc[2 * k + 1][3]);
        }

#pragma unroll
        for (int ks = 0; ks < 4; ks++) {
            uint32_t vb[8][2];
#pragma unroll
            for (int nt = 0; nt < 4; nt++) {
                const uint32_t off =
                    (uint32_t)((nt * 16 + (lid & 7) + ((lid & 16) ? 8 : 0)) * 128 +
                               (ks * 16 + ((lid & 8) ? 8 : 0)) * 2);
                uint32_t r0, r1, r2, r3;
                ldsm_x4(r0, r1, r2, r3, vb_base + SW128(off));
                vb[nt * 2][0] = r0; vb[nt * 2][1] = r1;
                vb[nt * 2 + 1][0] = r2; vb[nt * 2 + 1][1] = r3;
            }
#pragma unroll
            for (int j = 0; j < 8; j++) mma_f16(oacc[j], pa[ks], vb[j]);
        }
        __syncthreads();
    }

    const float inv0 = 1.f / l0, inv1 = 1.f / l1;
    const int qr0 = i0 + w * 16 + (lid >> 2);
    const size_t rb0 = (size_t)(bb * TFULL + qr0) * DM + h * 64;
    const size_t rb1 = rb0 + (size_t)8 * DM;
#pragma unroll
    for (int j = 0; j < 8; j++) {
        const int col = j * 8 + 2 * (lid & 3);
        *(uint32_t*)(O16 + rb0 + col) = pack_f16(oacc[j][0] * inv0, oacc[j][1] * inv0);
        *(uint32_t*)(O16 + rb1 + col) = pack_f16(oacc[j][2] * inv1, oacc[j][3] * inv1);
    }
#undef ISSUE_KV
}

// ===========================================================================
extern "C" void kernel_launch(void* const* d_in, const int* in_sizes, int n_in,
                              void* d_out, int out_size) {
    const float* x  = (const float*)d_in[0];
    const float* WQ = (const float*)d_in[1];
    const float* WK = (const float*)d_in[2];
    const float* WV = (const float*)d_in[3];
    const float* WO = (const float*)d_in[4];
    const int* tpos = (const int*)d_in[5];

    float* qkv;
    __half *x16, *wc16, *wo16, *att16, *q16, *k16, *v16t;
    cudaGetSymbolAddress((void**)&qkv, g_qkv);
    cudaGetSymbolAddress((void**)&x16, g_x16);
    cudaGetSymbolAddress((void**)&wc16, g_wc16);
    cudaGetSymbolAddress((void**)&wo16, g_wo16);
    cudaGetSymbolAddress((void**)&att16, g_att16);
    cudaGetSymbolAddress((void**)&q16, g_q16);
    cudaGetSymbolAddress((void**)&k16, g_k16);
    cudaGetSymbolAddress((void**)&v16t, g_v16t);

    cudaFuncSetAttribute(gemm_f16, cudaFuncAttributeMaxDynamicSharedMemorySize,
                         SM_GEMM);

    convert_all<<<6656, 256>>>((const float4*)x, (const float4*)WQ, (const float4*)WK,
                               (const float4*)WV, (const float4*)WO,
                               x16, wc16, wo16);

    // QKV projection: [4096,1536] = x @ Wcat^T, ldc=1536
    gemm_f16<<<dim3(12, 32), 256, SM_GEMM>>>(x16, wc16, qkv, LDQKV);

    rope_fp16<<<2 * TFULL, 128>>>(qkv, tpos, q16, k16, v16t);

    attn_mma<<<dim3(TFULL / 64, 16, 2), 128>>>(q16, k16, v16t, att16);

    // Output projection straight into d_out
    gemm_f16<<<dim3(8, 32), 256, SM_GEMM>>>(att16, wo16, (float*)d_out, DM);
}